// round 1
// baseline (speedup 1.0000x reference)
#include <cuda_runtime.h>
#include <cuda_bf16.h>

// Problem constants
#define B_ROWS   16384
#define D_DIM    2048
#define L_LAYERS 3
#define E_EXP    8
#define R_RANK   64
#define N_UV     512                      // E*R
#define N_TOTAL  (2*N_UV + E_EXP)         // 1032: [U cols | V cols | gate cols]
#define Y_STRIDE N_TOTAL

// Scratch: Y[b, n] for one layer at a time (67.6 MB)
__device__ float g_Y[(size_t)B_ROWS * Y_STRIDE];

// ---------------------------------------------------------------------------
// GEMM: Y[b, n] = sum_d Xi[b, d] * W_n[d]
//   n in [0,512)      -> U[l, n/64, n%64, :]
//   n in [512,1024)   -> V[l, ., ., :]
//   n in [1024,1032)  -> Wg[l, n-1024, :]
// Tiling: BM=128, BN=64, BK=16, 256 threads, 8x4 per-thread microtile.
// ---------------------------------------------------------------------------
#define BM 128
#define BN 64
#define BK 16

__global__ __launch_bounds__(256) void gemm_kernel(
    const float* __restrict__ Xi,
    const float* __restrict__ U,
    const float* __restrict__ V,
    const float* __restrict__ Wg,
    int layer)
{
    __shared__ float As[BK][BM];
    __shared__ float Bs[BK][BN];

    const int tid = threadIdx.x;
    const int m0 = blockIdx.y * BM;
    const int n0 = blockIdx.x * BN;

    // --- B-tile load mapping: thread -> (column nl, k quad) ---
    // 4 consecutive threads cover 16 consecutive k's of one weight row (float4 each).
    const int nl = tid >> 2;            // 0..63
    const int k4 = (tid & 3) * 4;       // 0,4,8,12
    const int n  = n0 + nl;
    const bool nvalid = (n < N_TOTAL);
    const float* wptr = Wg;             // safe dummy
    if (nvalid) {
        if (n < N_UV)            wptr = U  + ((size_t)layer * N_UV + n) * D_DIM;
        else if (n < 2 * N_UV)   wptr = V  + ((size_t)layer * N_UV + (n - N_UV)) * D_DIM;
        else                     wptr = Wg + ((size_t)layer * E_EXP + (n - 2 * N_UV)) * D_DIM;
    }

    // --- A-tile load mapping: thread loads 8 consecutive floats of row ra ---
    const int ra = tid >> 1;            // 0..127
    const int ca = (tid & 1) * 8;       // 0 or 8
    const float* arow = Xi + (size_t)(m0 + ra) * D_DIM;

    // --- compute mapping: 16x16 thread grid, 8 rows x 4 cols each ---
    const int ty = tid >> 4;            // 0..15 (m)
    const int tx = tid & 15;            // 0..15 (n)

    float acc[8][4];
    #pragma unroll
    for (int i = 0; i < 8; i++)
        #pragma unroll
        for (int j = 0; j < 4; j++) acc[i][j] = 0.f;

    for (int k0 = 0; k0 < D_DIM; k0 += BK) {
        // load A tile (transposed into smem: As[k][m])
        float4 a0 = *reinterpret_cast<const float4*>(arow + k0 + ca);
        float4 a1 = *reinterpret_cast<const float4*>(arow + k0 + ca + 4);
        As[ca + 0][ra] = a0.x; As[ca + 1][ra] = a0.y;
        As[ca + 2][ra] = a0.z; As[ca + 3][ra] = a0.w;
        As[ca + 4][ra] = a1.x; As[ca + 5][ra] = a1.y;
        As[ca + 6][ra] = a1.z; As[ca + 7][ra] = a1.w;

        // load B tile
        float4 bv = make_float4(0.f, 0.f, 0.f, 0.f);
        if (nvalid) bv = *reinterpret_cast<const float4*>(wptr + k0 + k4);
        Bs[k4 + 0][nl] = bv.x; Bs[k4 + 1][nl] = bv.y;
        Bs[k4 + 2][nl] = bv.z; Bs[k4 + 3][nl] = bv.w;

        __syncthreads();

        #pragma unroll
        for (int kk = 0; kk < BK; kk++) {
            float ar[8], br[4];
            #pragma unroll
            for (int i = 0; i < 8; i++) ar[i] = As[kk][ty * 8 + i];
            #pragma unroll
            for (int j = 0; j < 4; j++) br[j] = Bs[kk][tx * 4 + j];
            #pragma unroll
            for (int i = 0; i < 8; i++)
                #pragma unroll
                for (int j = 0; j < 4; j++)
                    acc[i][j] += ar[i] * br[j];
        }
        __syncthreads();
    }

    // store
    #pragma unroll
    for (int i = 0; i < 8; i++) {
        const int m = m0 + ty * 8 + i;
        #pragma unroll
        for (int j = 0; j < 4; j++) {
            const int nn = n0 + tx * 4 + j;
            if (nn < N_TOTAL)
                g_Y[(size_t)m * Y_STRIDE + nn] = acc[i][j];
        }
    }
}

// ---------------------------------------------------------------------------
// Row reduce + residual update.
// One block (256 thr) per row b:
//   esum[e] = sum_r Y[b, e*64+r] * Y[b, 512 + e*64+r]
//   gate    = softmax(Y[b,1024..1031] + bg[l])
//   xw      = sum_e esum[e]*gate[e]
//   Xi[b,:] += X0[b,:] * xw
// ---------------------------------------------------------------------------
__global__ __launch_bounds__(256) void row_update_kernel(
    const float* __restrict__ X0,
    const float* __restrict__ bg,
    float* __restrict__ Xi,
    int layer)
{
    const int b = blockIdx.x;
    const int t = threadIdx.x;
    __shared__ float esum[E_EXP];
    __shared__ float s_xw;
    if (t < E_EXP) esum[t] = 0.f;
    __syncthreads();

    const float* yrow = g_Y + (size_t)b * Y_STRIDE;

    // i = t (experts 0..3) and i = t+256 (experts 4..7); pair U col i with V col 512+i
    float p0 = yrow[t]       * yrow[N_UV + t];
    float p1 = yrow[256 + t] * yrow[N_UV + 256 + t];
    #pragma unroll
    for (int off = 16; off; off >>= 1) {
        p0 += __shfl_down_sync(0xffffffffu, p0, off);
        p1 += __shfl_down_sync(0xffffffffu, p1, off);
    }
    const int w = t >> 5;   // warp id: warp w covers i in [32w, 32w+32) -> e = w/2 (and 4 + w/2)
    if ((t & 31) == 0) {
        atomicAdd(&esum[w >> 1], p0);
        atomicAdd(&esum[4 + (w >> 1)], p1);
    }
    __syncthreads();

    if (t == 0) {
        float logits[E_EXP], mx = -1e30f;
        #pragma unroll
        for (int e = 0; e < E_EXP; e++) {
            logits[e] = yrow[2 * N_UV + e] + bg[layer * E_EXP + e];
            mx = fmaxf(mx, logits[e]);
        }
        float se = 0.f, xw = 0.f;
        #pragma unroll
        for (int e = 0; e < E_EXP; e++) {
            float g = expf(logits[e] - mx);
            se += g;
            xw += g * esum[e];
        }
        s_xw = xw / se;
    }
    __syncthreads();

    const float xw = s_xw;
    float4* xi4 = reinterpret_cast<float4*>(Xi) + (size_t)b * (D_DIM / 4);
    const float4* x04 = reinterpret_cast<const float4*>(X0) + (size_t)b * (D_DIM / 4);
    #pragma unroll
    for (int c = 0; c < 2; c++) {
        const int j = t + c * 256;
        float4 x = x04[j];
        float4 y = xi4[j];
        y.x += x.x * xw; y.y += x.y * xw;
        y.z += x.z * xw; y.w += x.w * xw;
        xi4[j] = y;
    }
}

// ---------------------------------------------------------------------------
// Launch: Xi lives in d_out. Init Xi = X0, then 3x (gemm -> row_update).
// All async, graph-capturable, allocation-free.
// ---------------------------------------------------------------------------
extern "C" void kernel_launch(void* const* d_in, const int* in_sizes, int n_in,
                              void* d_out, int out_size) {
    const float* X0 = (const float*)d_in[0];
    const float* U  = (const float*)d_in[1];
    const float* V  = (const float*)d_in[2];
    const float* Wg = (const float*)d_in[3];
    const float* bg = (const float*)d_in[4];
    float* Xi = (float*)d_out;

    cudaMemcpyAsync(Xi, X0, (size_t)B_ROWS * D_DIM * sizeof(float),
                    cudaMemcpyDeviceToDevice);

    dim3 ggrid((N_TOTAL + BN - 1) / BN, B_ROWS / BM);  // (17, 128)
    for (int l = 0; l < L_LAYERS; l++) {
        gemm_kernel<<<ggrid, 256>>>(Xi, U, V, Wg, l);
        row_update_kernel<<<B_ROWS, 256>>>(X0, bg, Xi, l);
    }
}

// round 3
// speedup vs baseline: 2.0024x; 2.0024x over previous
#include <cuda_runtime.h>
#include <cuda_bf16.h>
#include <cstdint>

// ---------------------------------------------------------------------------
// Problem constants
// ---------------------------------------------------------------------------
#define B_ROWS   16384
#define D_DIM    2048
#define L_LAYERS 3
#define E_EXP    8
#define NCOL     (L_LAYERS * 1024)   // 3072 interleaved U/V columns (all layers)
#define NEXP     (L_LAYERS * E_EXP)  // 24

// GEMM tiling
#define BM 128
#define BN 128
#define KB 64                         // bf16 per k-step (128 B rows)
#define STAGES 4
#define KSTEPS (D_DIM / KB)           // 32
#define NSTEPS (3 * KSTEPS)           // 96: phases hh, lh, hl
#define A_BYTES (BM * 128)            // 16 KB
#define B_BYTES (BN * 128)            // 16 KB
#define STAGE_BYTES (A_BYTES + B_BYTES)
#define SMEM_TOTAL (STAGES * STAGE_BYTES)   // 128 KB

// ---------------------------------------------------------------------------
// Device scratch (static)
// ---------------------------------------------------------------------------
__device__ __nv_bfloat16 g_Ahi[(size_t)B_ROWS * D_DIM];
__device__ __nv_bfloat16 g_Alo[(size_t)B_ROWS * D_DIM];
__device__ __nv_bfloat16 g_Bhi[(size_t)NCOL * D_DIM];
__device__ __nv_bfloat16 g_Blo[(size_t)NCOL * D_DIM];
__device__ float         g_e0[(size_t)B_ROWS * NEXP];

// ---------------------------------------------------------------------------
// Helpers
// ---------------------------------------------------------------------------
__device__ __forceinline__ uint32_t smem_u32(const void* p) {
    uint32_t a;
    asm("{ .reg .u64 t; cvta.to.shared.u64 t, %1; cvt.u32.u64 %0, t; }"
        : "=r"(a) : "l"(p));
    return a;
}
__device__ __forceinline__ uint32_t swz(uint32_t off) {        // SW128
    return off ^ ((off >> 3) & 0x70);
}
__device__ __forceinline__ void cpa16(uint32_t dst, const void* src) {
    asm volatile("cp.async.cg.shared.global [%0], [%1], 16;"
                 :: "r"(dst), "l"(src) : "memory");
}
__device__ __forceinline__ void cpa_commit() {
    asm volatile("cp.async.commit_group;" ::: "memory");
}
__device__ __forceinline__ void cpa_wait2() {
    asm volatile("cp.async.wait_group 2;" ::: "memory");
}
__device__ __forceinline__ void ldsm_x4(uint32_t* r, uint32_t addr) {
    asm volatile("ldmatrix.sync.aligned.m8n8.x4.shared.b16 {%0,%1,%2,%3}, [%4];"
                 : "=r"(r[0]), "=r"(r[1]), "=r"(r[2]), "=r"(r[3]) : "r"(addr));
}
__device__ __forceinline__ void mma16816(float* d, const uint32_t* a,
                                         uint32_t b0, uint32_t b1) {
    asm volatile(
        "mma.sync.aligned.m16n8k16.row.col.f32.bf16.bf16.f32 "
        "{%0,%1,%2,%3}, {%4,%5,%6,%7}, {%8,%9}, {%0,%1,%2,%3};"
        : "+f"(d[0]), "+f"(d[1]), "+f"(d[2]), "+f"(d[3])
        : "r"(a[0]), "r"(a[1]), "r"(a[2]), "r"(a[3]), "r"(b0), "r"(b1));
}

// ---------------------------------------------------------------------------
// Weight prep: (U,V) fp32 -> interleaved-pair bf16 hi/lo, K-contiguous rows.
// Global col n in [0, 3072): l=n>>10, within-layer c=n&1023: e=c>>7, i=c&127,
// r=i>>1, uv=i&1 (even=U, odd=V). One block per column.
// ---------------------------------------------------------------------------
__global__ __launch_bounds__(256) void prep_weights(
    const float* __restrict__ U, const float* __restrict__ V)
{
    const int row = blockIdx.x;
    const int l = row >> 10, c = row & 1023;
    const int e = c >> 7, i = c & 127, r = i >> 1, uv = i & 1;
    const float* src = (uv ? V : U) + (((size_t)(l * E_EXP + e)) * 64 + r) * D_DIM;
    const size_t dst = (size_t)row * D_DIM;
    const int k = threadIdx.x * 8;
    float4 a = *reinterpret_cast<const float4*>(src + k);
    float4 b = *reinterpret_cast<const float4*>(src + k + 4);
    float v[8] = {a.x, a.y, a.z, a.w, b.x, b.y, b.z, b.w};
    __nv_bfloat16 hi[8], lo[8];
#pragma unroll
    for (int j = 0; j < 8; j++) {
        hi[j] = __float2bfloat16(v[j]);
        lo[j] = __float2bfloat16(v[j] - __bfloat162float(hi[j]));
    }
    *reinterpret_cast<uint4*>(&g_Bhi[dst + k]) = *reinterpret_cast<uint4*>(hi);
    *reinterpret_cast<uint4*>(&g_Blo[dst + k]) = *reinterpret_cast<uint4*>(lo);
}

// ---------------------------------------------------------------------------
// X0 split (done once; Xi never materialized until finalize).
// ---------------------------------------------------------------------------
__global__ __launch_bounds__(256) void split_x0(const float* __restrict__ X0)
{
    const size_t base = ((size_t)blockIdx.x * 256 + threadIdx.x) * 16;
#pragma unroll
    for (int cidx = 0; cidx < 4; cidx++) {
        const size_t idx = base + cidx * 4;
        float4 v = *reinterpret_cast<const float4*>(X0 + idx);
        float vv[4] = {v.x, v.y, v.z, v.w};
        __nv_bfloat16 hi[4], lo[4];
#pragma unroll
        for (int j = 0; j < 4; j++) {
            hi[j] = __float2bfloat16(vv[j]);
            lo[j] = __float2bfloat16(vv[j] - __bfloat162float(hi[j]));
        }
        *reinterpret_cast<uint2*>(&g_Ahi[idx]) = *reinterpret_cast<uint2*>(hi);
        *reinterpret_cast<uint2*>(&g_Alo[idx]) = *reinterpret_cast<uint2*>(lo);
    }
}

// ---------------------------------------------------------------------------
// HMMA GEMM with fused expert-sum epilogue.
// Grid (24 n-tiles, 128 m-tiles), 256 threads (8 warps: 2 m x 4 n).
// K loop: 96 steps of 64 bf16 = 3 precision phases (AhiBhi, AloBhi, AhiBlo).
// Epilogue: e0[b, nt] = sum over 64 (U,V) column pairs of the 128-wide tile.
// ---------------------------------------------------------------------------
__global__ __launch_bounds__(256) void gemm_hmma()
{
    extern __shared__ char smem[];
    const uint32_t sb = smem_u32(smem);
    const int tid = threadIdx.x;
    const int lane = tid & 31, warp = tid >> 5;
    const int wm = warp & 1, wn = warp >> 1;     // warp tile 64m x 32n
    const int nt = blockIdx.x;                    // 0..23  (layer*8 + expert)
    const int m0 = blockIdx.y * BM;
    const size_t brow0 = (size_t)nt * BN;

    // cp.async mappings (4 x 16B chunks per tile per thread)
    const int lr = tid >> 1;                      // 0..127 (row in tile)
    const int lc = (tid & 1) * 64;                // byte col 0 or 64

    float acc[4][4][4];
#pragma unroll
    for (int mi = 0; mi < 4; mi++)
#pragma unroll
        for (int ni = 0; ni < 4; ni++)
#pragma unroll
            for (int j = 0; j < 4; j++) acc[mi][ni][j] = 0.f;

    auto load_stage = [&](int step) {
        if (step < NSTEPS) {
            const int p = step / KSTEPS;
            const int k0 = (step % KSTEPS) * KB;
            const __nv_bfloat16* Asrc = (p == 1) ? g_Alo : g_Ahi;
            const __nv_bfloat16* Bsrc = (p == 2) ? g_Blo : g_Bhi;
            const uint32_t a_base = sb + (step & (STAGES - 1)) * STAGE_BYTES;
            const uint32_t b_base = a_base + A_BYTES;
            const __nv_bfloat16* ap = Asrc + (size_t)(m0 + lr) * D_DIM + k0 + lc / 2;
            const __nv_bfloat16* bp = Bsrc + (brow0 + lr) * D_DIM + k0 + lc / 2;
#pragma unroll
            for (int i = 0; i < 4; i++)
                cpa16(a_base + swz(lr * 128 + lc + i * 16), ap + i * 8);
#pragma unroll
            for (int i = 0; i < 4; i++)
                cpa16(b_base + swz(lr * 128 + lc + i * 16), bp + i * 8);
        }
        cpa_commit();
    };

    load_stage(0); load_stage(1); load_stage(2);

    const int arow = wm * 64 + (lane & 15);
    const int brow = wn * 32 + (lane & 15);
    const int khalf = (lane >> 4) * 16;

    for (int step = 0; step < NSTEPS; ++step) {
        cpa_wait2();
        __syncthreads();
        load_stage(step + 3);

        const uint32_t a_base = sb + (step & (STAGES - 1)) * STAGE_BYTES;
        const uint32_t b_base = a_base + A_BYTES;
#pragma unroll
        for (int k16 = 0; k16 < 4; k16++) {
            const int kb = k16 * 32 + khalf;
            uint32_t a[4][4], bb[2][4];
#pragma unroll
            for (int mi = 0; mi < 4; mi++)
                ldsm_x4(a[mi], a_base + swz((arow + mi * 16) * 128 + kb));
#pragma unroll
            for (int nj = 0; nj < 2; nj++)
                ldsm_x4(bb[nj], b_base + swz((brow + nj * 16) * 128 + kb));
#pragma unroll
            for (int mi = 0; mi < 4; mi++)
#pragma unroll
                for (int ni = 0; ni < 4; ni++)
                    mma16816(acc[mi][ni], a[mi],
                             bb[ni >> 1][ni & 1], bb[ni >> 1][(ni & 1) + 2]);
        }
    }

    // ---- Fused epilogue: per-row sum of U*V pairs over this 128-col tile ----
    // d-frag: d0=(row=lane/4, col=(lane%4)*2), d1=col+1 (the V partner),
    //         d2/d3 same at row+8. Pair products are thread-local.
    __syncthreads();
    float* esum = reinterpret_cast<float*>(smem);
    if (tid < BM) esum[tid] = 0.f;
    __syncthreads();

#pragma unroll
    for (int mi = 0; mi < 4; mi++) {
        float pl = 0.f, ph = 0.f;
#pragma unroll
        for (int ni = 0; ni < 4; ni++) {
            pl += acc[mi][ni][0] * acc[mi][ni][1];
            ph += acc[mi][ni][2] * acc[mi][ni][3];
        }
        pl += __shfl_xor_sync(0xffffffffu, pl, 1);
        pl += __shfl_xor_sync(0xffffffffu, pl, 2);
        ph += __shfl_xor_sync(0xffffffffu, ph, 1);
        ph += __shfl_xor_sync(0xffffffffu, ph, 2);
        if ((lane & 3) == 0) {
            const int r = wm * 64 + mi * 16 + (lane >> 2);
            atomicAdd(&esum[r], pl);
            atomicAdd(&esum[r + 8], ph);
        }
    }
    __syncthreads();
    if (tid < BM)
        g_e0[(size_t)(m0 + tid) * NEXP + nt] = esum[tid];
}

// ---------------------------------------------------------------------------
// Finalize: exact fp32 gate logits, per-row scalar recurrence, out = c * X0.
// ---------------------------------------------------------------------------
__global__ __launch_bounds__(256) void finalize(
    const float* __restrict__ X0, const float* __restrict__ Wg,
    const float* __restrict__ bg, float* __restrict__ out)
{
    __shared__ float xs[D_DIM];
    __shared__ float slog[NEXP];
    __shared__ float sc;
    const int b = blockIdx.x, t = threadIdx.x;
    const int w = t >> 5, lane = t & 31;

    float4* xs4 = reinterpret_cast<float4*>(xs);
    const float4* x04 = reinterpret_cast<const float4*>(X0 + (size_t)b * D_DIM);
    xs4[t] = x04[t];
    xs4[t + 256] = x04[t + 256];
    __syncthreads();

    // 24 gate dot-products: warp w handles logits 3w .. 3w+2
#pragma unroll
    for (int j = 0; j < 3; j++) {
        const int gl = w * 3 + j;
        const float* wg = Wg + (size_t)gl * D_DIM;
        float s = 0.f;
#pragma unroll 8
        for (int k = lane; k < D_DIM; k += 32) s += xs[k] * wg[k];
#pragma unroll
        for (int off = 16; off; off >>= 1)
            s += __shfl_down_sync(0xffffffffu, s, off);
        if (lane == 0) slog[gl] = s;
    }
    __syncthreads();

    if (t == 0) {
        const float* e0 = g_e0 + (size_t)b * NEXP;
        float c = 1.f;
#pragma unroll
        for (int l = 0; l < L_LAYERS; l++) {
            const int base = l * E_EXP;
            float logit[E_EXP], mx = -1e30f;
#pragma unroll
            for (int e = 0; e < E_EXP; e++) {
                logit[e] = c * slog[base + e] + bg[base + e];
                mx = fmaxf(mx, logit[e]);
            }
            float se = 0.f, acc = 0.f;
#pragma unroll
            for (int e = 0; e < E_EXP; e++) {
                const float ge = expf(logit[e] - mx);
                se += ge;
                acc += ge * e0[base + e];
            }
            c += c * c * (acc / se);
        }
        sc = c;
    }
    __syncthreads();

    const float c = sc;
    float4* o4 = reinterpret_cast<float4*>(out + (size_t)b * D_DIM);
#pragma unroll
    for (int cidx = 0; cidx < 2; cidx++) {
        const int j = t + cidx * 256;
        float4 x = xs4[j];
        x.x *= c; x.y *= c; x.z *= c; x.w *= c;
        o4[j] = x;
    }
}

// ---------------------------------------------------------------------------
// Launch: 4 kernels total, no layer loop on device-dependency path.
// ---------------------------------------------------------------------------
extern "C" void kernel_launch(void* const* d_in, const int* in_sizes, int n_in,
                              void* d_out, int out_size) {
    const float* X0 = (const float*)d_in[0];
    const float* U  = (const float*)d_in[1];
    const float* V  = (const float*)d_in[2];
    const float* Wg = (const float*)d_in[3];
    const float* bg = (const float*)d_in[4];
    float* out = (float*)d_out;

    cudaFuncSetAttribute(gemm_hmma, cudaFuncAttributeMaxDynamicSharedMemorySize,
                         SMEM_TOTAL);

    prep_weights<<<NCOL, 256>>>(U, V);
    split_x0<<<(B_ROWS * D_DIM) / (256 * 16), 256>>>(X0);
    gemm_hmma<<<dim3(NEXP, B_ROWS / BM), 256, SMEM_TOTAL>>>();
    finalize<<<B_ROWS, 256>>>(X0, Wg, bg, out);
}

// round 4
// speedup vs baseline: 2.7272x; 1.3619x over previous
#include <cuda_runtime.h>
#include <cuda_bf16.h>
#include <cstdint>

// ---------------------------------------------------------------------------
// Problem constants
// ---------------------------------------------------------------------------
#define B_ROWS   16384
#define D_DIM    2048
#define L_LAYERS 3
#define E_EXP    8
#define NCOL     (L_LAYERS * 1024)   // 3072 interleaved U/V columns (all layers)
#define NEXP     (L_LAYERS * E_EXP)  // 24

// GEMM tiling
#define BM 128
#define BN 256
#define KB 64                         // bf16 per k-step (128 B rows)
#define STAGES 4
#define KSTEPS (D_DIM / KB)           // 32
#define NSTEPS (3 * KSTEPS)           // 96: phases hh, lh, hl
#define A_BYTES (BM * 128)            // 16 KB
#define B_BYTES (BN * 128)            // 32 KB
#define STAGE_BYTES (A_BYTES + B_BYTES)
#define SMEM_TOTAL (STAGES * STAGE_BYTES)   // 192 KB

// ---------------------------------------------------------------------------
// Device scratch (static)
// ---------------------------------------------------------------------------
__device__ __nv_bfloat16 g_Ahi[(size_t)B_ROWS * D_DIM];
__device__ __nv_bfloat16 g_Alo[(size_t)B_ROWS * D_DIM];
__device__ __nv_bfloat16 g_Bhi[(size_t)NCOL * D_DIM];
__device__ __nv_bfloat16 g_Blo[(size_t)NCOL * D_DIM];
__device__ float         g_e0[(size_t)B_ROWS * NEXP];
__device__ float         g_logit[(size_t)B_ROWS * NEXP];

// ---------------------------------------------------------------------------
// Helpers
// ---------------------------------------------------------------------------
__device__ __forceinline__ uint32_t smem_u32(const void* p) {
    uint32_t a;
    asm("{ .reg .u64 t; cvta.to.shared.u64 t, %1; cvt.u32.u64 %0, t; }"
        : "=r"(a) : "l"(p));
    return a;
}
__device__ __forceinline__ uint32_t swz(uint32_t off) {        // SW128
    return off ^ ((off >> 3) & 0x70);
}
__device__ __forceinline__ void cpa16(uint32_t dst, const void* src) {
    asm volatile("cp.async.cg.shared.global [%0], [%1], 16;"
                 :: "r"(dst), "l"(src) : "memory");
}
__device__ __forceinline__ void cpa_commit() {
    asm volatile("cp.async.commit_group;" ::: "memory");
}
__device__ __forceinline__ void cpa_wait2() {
    asm volatile("cp.async.wait_group 2;" ::: "memory");
}
__device__ __forceinline__ void ldsm_x4(uint32_t* r, uint32_t addr) {
    asm volatile("ldmatrix.sync.aligned.m8n8.x4.shared.b16 {%0,%1,%2,%3}, [%4];"
                 : "=r"(r[0]), "=r"(r[1]), "=r"(r[2]), "=r"(r[3]) : "r"(addr));
}
__device__ __forceinline__ void mma16816(float* d, const uint32_t* a,
                                         uint32_t b0, uint32_t b1) {
    asm volatile(
        "mma.sync.aligned.m16n8k16.row.col.f32.bf16.bf16.f32 "
        "{%0,%1,%2,%3}, {%4,%5,%6,%7}, {%8,%9}, {%0,%1,%2,%3};"
        : "+f"(d[0]), "+f"(d[1]), "+f"(d[2]), "+f"(d[3])
        : "r"(a[0]), "r"(a[1]), "r"(a[2]), "r"(a[3]), "r"(b0), "r"(b1));
}

// ---------------------------------------------------------------------------
// Weight prep: (U,V) fp32 -> interleaved-pair bf16 hi/lo, K-contiguous rows.
// ---------------------------------------------------------------------------
__global__ __launch_bounds__(256) void prep_weights(
    const float* __restrict__ U, const float* __restrict__ V)
{
    const int row = blockIdx.x;
    const int l = row >> 10, c = row & 1023;
    const int e = c >> 7, i = c & 127, r = i >> 1, uv = i & 1;
    const float* src = (uv ? V : U) + (((size_t)(l * E_EXP + e)) * 64 + r) * D_DIM;
    const size_t dst = (size_t)row * D_DIM;
    const int k = threadIdx.x * 8;
    float4 a = *reinterpret_cast<const float4*>(src + k);
    float4 b = *reinterpret_cast<const float4*>(src + k + 4);
    float v[8] = {a.x, a.y, a.z, a.w, b.x, b.y, b.z, b.w};
    __nv_bfloat16 hi[8], lo[8];
#pragma unroll
    for (int j = 0; j < 8; j++) {
        hi[j] = __float2bfloat16(v[j]);
        lo[j] = __float2bfloat16(v[j] - __bfloat162float(hi[j]));
    }
    *reinterpret_cast<uint4*>(&g_Bhi[dst + k]) = *reinterpret_cast<uint4*>(hi);
    *reinterpret_cast<uint4*>(&g_Blo[dst + k]) = *reinterpret_cast<uint4*>(lo);
}

// ---------------------------------------------------------------------------
// X0 split.
// ---------------------------------------------------------------------------
__global__ __launch_bounds__(256) void split_x0(const float* __restrict__ X0)
{
    const size_t base = ((size_t)blockIdx.x * 256 + threadIdx.x) * 16;
#pragma unroll
    for (int cidx = 0; cidx < 4; cidx++) {
        const size_t idx = base + cidx * 4;
        float4 v = *reinterpret_cast<const float4*>(X0 + idx);
        float vv[4] = {v.x, v.y, v.z, v.w};
        __nv_bfloat16 hi[4], lo[4];
#pragma unroll
        for (int j = 0; j < 4; j++) {
            hi[j] = __float2bfloat16(vv[j]);
            lo[j] = __float2bfloat16(vv[j] - __bfloat162float(hi[j]));
        }
        *reinterpret_cast<uint2*>(&g_Ahi[idx]) = *reinterpret_cast<uint2*>(hi);
        *reinterpret_cast<uint2*>(&g_Alo[idx]) = *reinterpret_cast<uint2*>(lo);
    }
}

// ---------------------------------------------------------------------------
// Gate logits: fp32 skinny GEMM, logit0[b, gl] = X0[b,:] . Wg[gl,:].
// 128 blocks x 256 thr; block = 128 rows; 2 threads/row x 12 logits.
// ---------------------------------------------------------------------------
#define GL_BM 128
#define GL_BK 64
__global__ __launch_bounds__(256) void gate_logits(
    const float* __restrict__ X0, const float* __restrict__ Wg)
{
    __shared__ float As[GL_BK][GL_BM + 1];
    __shared__ float Ws[GL_BK][36];
    const int tid = threadIdx.x;
    const int m0 = blockIdx.x * GL_BM;
    const int row = tid >> 1;
    const int ch = (tid & 1) * 12;
    float acc[12];
#pragma unroll
    for (int j = 0; j < 12; j++) acc[j] = 0.f;

    for (int kc = 0; kc < D_DIM; kc += GL_BK) {
#pragma unroll
        for (int i = 0; i < 8; i++) {
            const int idx = i * 256 + tid;
            const int r = idx >> 4, c4 = (idx & 15) * 4;
            float4 v = *reinterpret_cast<const float4*>(
                X0 + (size_t)(m0 + r) * D_DIM + kc + c4);
            As[c4 + 0][r] = v.x; As[c4 + 1][r] = v.y;
            As[c4 + 2][r] = v.z; As[c4 + 3][r] = v.w;
        }
#pragma unroll
        for (int i = 0; i < 2; i++) {
            const int idx = i * 256 + tid;
            if (idx < 384) {
                const int r = idx >> 4, c4 = (idx & 15) * 4;
                float4 v = *reinterpret_cast<const float4*>(
                    Wg + (size_t)r * D_DIM + kc + c4);
                Ws[c4 + 0][r] = v.x; Ws[c4 + 1][r] = v.y;
                Ws[c4 + 2][r] = v.z; Ws[c4 + 3][r] = v.w;
            }
        }
        __syncthreads();
#pragma unroll 8
        for (int kk = 0; kk < GL_BK; kk++) {
            const float a = As[kk][row];
            float4 w0 = *reinterpret_cast<float4*>(&Ws[kk][ch]);
            float4 w1 = *reinterpret_cast<float4*>(&Ws[kk][ch + 4]);
            float4 w2 = *reinterpret_cast<float4*>(&Ws[kk][ch + 8]);
            acc[0] += a * w0.x; acc[1] += a * w0.y;
            acc[2] += a * w0.z; acc[3] += a * w0.w;
            acc[4] += a * w1.x; acc[5] += a * w1.y;
            acc[6] += a * w1.z; acc[7] += a * w1.w;
            acc[8] += a * w2.x; acc[9] += a * w2.y;
            acc[10] += a * w2.z; acc[11] += a * w2.w;
        }
        __syncthreads();
    }
    float* dst = g_logit + (size_t)(m0 + row) * NEXP + ch;
#pragma unroll
    for (int j = 0; j < 12; j++) dst[j] = acc[j];
}

// ---------------------------------------------------------------------------
// HMMA GEMM with fused expert-sum epilogue.
// Grid (12 n-tiles, 128 m-tiles), 256 threads = 8 warps (2m x 4n),
// warp tile 64m x 64n. Tile nt covers global experts 2nt, 2nt+1.
// ---------------------------------------------------------------------------
__global__ __launch_bounds__(256) void gemm_hmma()
{
    extern __shared__ char smem[];
    const uint32_t sb = smem_u32(smem);
    const int tid = threadIdx.x;
    const int lane = tid & 31, warp = tid >> 5;
    const int wm = warp & 1, wn = warp >> 1;     // 2m x 4n
    const int nt = blockIdx.x;                    // 0..11
    const int m0 = blockIdx.y * BM;
    const size_t brow0 = (size_t)nt * BN;

    float acc[4][8][4];
#pragma unroll
    for (int mi = 0; mi < 4; mi++)
#pragma unroll
        for (int ni = 0; ni < 8; ni++)
#pragma unroll
            for (int j = 0; j < 4; j++) acc[mi][ni][j] = 0.f;

    auto load_stage = [&](int step) {
        if (step < NSTEPS) {
            const int p = (step >= 2 * KSTEPS) ? 2 : (step >= KSTEPS ? 1 : 0);
            const int k0 = (step - p * KSTEPS) * KB;
            const __nv_bfloat16* Asrc = (p == 1) ? g_Alo : g_Ahi;
            const __nv_bfloat16* Bsrc = (p == 2) ? g_Blo : g_Bhi;
            const uint32_t a_base = sb + (step & (STAGES - 1)) * STAGE_BYTES;
            const uint32_t b_base = a_base + A_BYTES;
#pragma unroll
            for (int i = 0; i < 4; i++) {
                const int idx = i * 256 + tid;
                const int r = idx >> 3, c = idx & 7;
                cpa16(a_base + swz(r * 128 + c * 16),
                      Asrc + (size_t)(m0 + r) * D_DIM + k0 + c * 8);
            }
#pragma unroll
            for (int i = 0; i < 8; i++) {
                const int idx = i * 256 + tid;
                const int r = idx >> 3, c = idx & 7;
                cpa16(b_base + swz(r * 128 + c * 16),
                      Bsrc + (brow0 + r) * D_DIM + k0 + c * 8);
            }
        }
        cpa_commit();
    };

    load_stage(0); load_stage(1); load_stage(2);

    const int arow = wm * 64 + (lane & 15);
    const int brow = wn * 64 + (lane & 15);
    const int khalf = (lane >> 4) * 16;

    for (int step = 0; step < NSTEPS; ++step) {
        cpa_wait2();
        __syncthreads();
        load_stage(step + 3);

        const uint32_t a_base = sb + (step & (STAGES - 1)) * STAGE_BYTES;
        const uint32_t b_base = a_base + A_BYTES;
#pragma unroll
        for (int k16 = 0; k16 < 4; k16++) {
            const int kb = k16 * 32 + khalf;
            uint32_t a[4][4], bb[4][4];
#pragma unroll
            for (int mi = 0; mi < 4; mi++)
                ldsm_x4(a[mi], a_base + swz((arow + mi * 16) * 128 + kb));
#pragma unroll
            for (int nj = 0; nj < 4; nj++)
                ldsm_x4(bb[nj], b_base + swz((brow + nj * 16) * 128 + kb));
#pragma unroll
            for (int mi = 0; mi < 4; mi++)
#pragma unroll
                for (int ni = 0; ni < 8; ni++)
                    mma16816(acc[mi][ni], a[mi],
                             bb[ni >> 1][ni & 1], bb[ni >> 1][(ni & 1) + 2]);
        }
    }

    // ---- Fused epilogue: pair products -> per-row per-expert sums ----
    __syncthreads();
    float* esum = reinterpret_cast<float*>(smem);   // [128][2]
    esum[tid] = 0.f;                                 // 256 floats
    __syncthreads();

    const int eloc = wn >> 1;                        // expert within tile (0/1)
#pragma unroll
    for (int mi = 0; mi < 4; mi++) {
        float pl = 0.f, ph = 0.f;
#pragma unroll
        for (int ni = 0; ni < 8; ni++) {
            pl += acc[mi][ni][0] * acc[mi][ni][1];
            ph += acc[mi][ni][2] * acc[mi][ni][3];
        }
        pl += __shfl_xor_sync(0xffffffffu, pl, 1);
        pl += __shfl_xor_sync(0xffffffffu, pl, 2);
        ph += __shfl_xor_sync(0xffffffffu, ph, 1);
        ph += __shfl_xor_sync(0xffffffffu, ph, 2);
        if ((lane & 3) == 0) {
            const int r = wm * 64 + mi * 16 + (lane >> 2);
            atomicAdd(&esum[r * 2 + eloc], pl);
            atomicAdd(&esum[(r + 8) * 2 + eloc], ph);
        }
    }
    __syncthreads();
    if (tid < BM) {
        const size_t b = (size_t)(m0 + tid);
        g_e0[b * NEXP + nt * 2 + 0] = esum[tid * 2 + 0];
        g_e0[b * NEXP + nt * 2 + 1] = esum[tid * 2 + 1];
    }
}

// ---------------------------------------------------------------------------
// Finalize: scalar recurrence from precomputed logits/e0, out = c * X0.
// ---------------------------------------------------------------------------
__global__ __launch_bounds__(256) void finalize(
    const float* __restrict__ X0, const float* __restrict__ bg,
    float* __restrict__ out)
{
    __shared__ float sc;
    const int b = blockIdx.x, t = threadIdx.x;

    if (t == 0) {
        const float* e0 = g_e0 + (size_t)b * NEXP;
        const float* lg = g_logit + (size_t)b * NEXP;
        float c = 1.f;
#pragma unroll
        for (int l = 0; l < L_LAYERS; l++) {
            const int base = l * E_EXP;
            float logit[E_EXP], mx = -1e30f;
#pragma unroll
            for (int e = 0; e < E_EXP; e++) {
                logit[e] = c * lg[base + e] + bg[base + e];
                mx = fmaxf(mx, logit[e]);
            }
            float se = 0.f, acc = 0.f;
#pragma unroll
            for (int e = 0; e < E_EXP; e++) {
                const float ge = expf(logit[e] - mx);
                se += ge;
                acc += ge * e0[base + e];
            }
            c += c * c * (acc / se);
        }
        sc = c;
    }
    __syncthreads();

    const float c = sc;
    const float4* x04 = reinterpret_cast<const float4*>(X0 + (size_t)b * D_DIM);
    float4* o4 = reinterpret_cast<float4*>(out + (size_t)b * D_DIM);
#pragma unroll
    for (int cidx = 0; cidx < 2; cidx++) {
        const int j = t + cidx * 256;
        float4 x = x04[j];
        x.x *= c; x.y *= c; x.z *= c; x.w *= c;
        o4[j] = x;
    }
}

// ---------------------------------------------------------------------------
// Launch
// ---------------------------------------------------------------------------
extern "C" void kernel_launch(void* const* d_in, const int* in_sizes, int n_in,
                              void* d_out, int out_size) {
    const float* X0 = (const float*)d_in[0];
    const float* U  = (const float*)d_in[1];
    const float* V  = (const float*)d_in[2];
    const float* Wg = (const float*)d_in[3];
    const float* bg = (const float*)d_in[4];
    float* out = (float*)d_out;

    cudaFuncSetAttribute(gemm_hmma, cudaFuncAttributeMaxDynamicSharedMemorySize,
                         SMEM_TOTAL);

    prep_weights<<<NCOL, 256>>>(U, V);
    split_x0<<<(B_ROWS * D_DIM) / (256 * 16), 256>>>(X0);
    gate_logits<<<B_ROWS / GL_BM, 256>>>(X0, Wg);
    gemm_hmma<<<dim3(NCOL / BN, B_ROWS / BM), 256, SMEM_TOTAL>>>();
    finalize<<<B_ROWS, 256>>>(X0, bg, out);
}

// round 5
// speedup vs baseline: 3.1388x; 1.1509x over previous
#include <cuda_runtime.h>
#include <cuda_bf16.h>
#include <cstdint>

// ---------------------------------------------------------------------------
// Problem constants
// ---------------------------------------------------------------------------
#define B_ROWS   16384
#define D_DIM    2048
#define L_LAYERS 3
#define E_EXP    8
#define NCOL     (L_LAYERS * 1024)   // 3072 interleaved U/V columns (all layers)
#define NEXP     (L_LAYERS * E_EXP)  // 24

// GEMM tiling: 128x128 tile, 4 warps (2m x 2n), 64x64 warp tile, 2 CTAs/SM.
#define BM 128
#define BN 128
#define KB 64                         // bf16 per k-step (128 B rows)
#define STAGES 3
#define KSTEPS (D_DIM / KB)           // 32
#define NSTEPS (3 * KSTEPS)           // 96: phases hh, lh, hl
#define A_BYTES (BM * 128)            // 16 KB
#define B_BYTES (BN * 128)            // 16 KB
#define STAGE_BYTES (A_BYTES + B_BYTES)      // 32 KB
#define SMEM_TOTAL (STAGES * STAGE_BYTES)    // 96 KB -> 2 CTAs/SM

// ---------------------------------------------------------------------------
// Device scratch (static)
// ---------------------------------------------------------------------------
__device__ __nv_bfloat16 g_Ahi[(size_t)B_ROWS * D_DIM];
__device__ __nv_bfloat16 g_Alo[(size_t)B_ROWS * D_DIM];
__device__ __nv_bfloat16 g_Bhi[(size_t)NCOL * D_DIM];
__device__ __nv_bfloat16 g_Blo[(size_t)NCOL * D_DIM];
__device__ float         g_e0[(size_t)B_ROWS * NEXP];
__device__ float         g_logit[(size_t)B_ROWS * NEXP];

// ---------------------------------------------------------------------------
// Helpers
// ---------------------------------------------------------------------------
__device__ __forceinline__ uint32_t smem_u32(const void* p) {
    uint32_t a;
    asm("{ .reg .u64 t; cvta.to.shared.u64 t, %1; cvt.u32.u64 %0, t; }"
        : "=r"(a) : "l"(p));
    return a;
}
__device__ __forceinline__ uint32_t swz(uint32_t off) {        // SW128
    return off ^ ((off >> 3) & 0x70);
}
__device__ __forceinline__ void cpa16(uint32_t dst, const void* src) {
    asm volatile("cp.async.cg.shared.global [%0], [%1], 16;"
                 :: "r"(dst), "l"(src) : "memory");
}
__device__ __forceinline__ void cpa_commit() {
    asm volatile("cp.async.commit_group;" ::: "memory");
}
__device__ __forceinline__ void cpa_wait1() {
    asm volatile("cp.async.wait_group 1;" ::: "memory");
}
__device__ __forceinline__ void ldsm_x4(uint32_t* r, uint32_t addr) {
    asm volatile("ldmatrix.sync.aligned.m8n8.x4.shared.b16 {%0,%1,%2,%3}, [%4];"
                 : "=r"(r[0]), "=r"(r[1]), "=r"(r[2]), "=r"(r[3]) : "r"(addr));
}
__device__ __forceinline__ void mma16816(float* d, const uint32_t* a,
                                         uint32_t b0, uint32_t b1) {
    asm volatile(
        "mma.sync.aligned.m16n8k16.row.col.f32.bf16.bf16.f32 "
        "{%0,%1,%2,%3}, {%4,%5,%6,%7}, {%8,%9}, {%0,%1,%2,%3};"
        : "+f"(d[0]), "+f"(d[1]), "+f"(d[2]), "+f"(d[3])
        : "r"(a[0]), "r"(a[1]), "r"(a[2]), "r"(a[3]), "r"(b0), "r"(b1));
}

// ---------------------------------------------------------------------------
// Weight prep: (U,V) fp32 -> interleaved-pair bf16 hi/lo, K-contiguous rows.
// ---------------------------------------------------------------------------
__global__ __launch_bounds__(256) void prep_weights(
    const float* __restrict__ U, const float* __restrict__ V)
{
    const int row = blockIdx.x;
    const int l = row >> 10, c = row & 1023;
    const int e = c >> 7, i = c & 127, r = i >> 1, uv = i & 1;
    const float* src = (uv ? V : U) + (((size_t)(l * E_EXP + e)) * 64 + r) * D_DIM;
    const size_t dst = (size_t)row * D_DIM;
    const int k = threadIdx.x * 8;
    float4 a = *reinterpret_cast<const float4*>(src + k);
    float4 b = *reinterpret_cast<const float4*>(src + k + 4);
    float v[8] = {a.x, a.y, a.z, a.w, b.x, b.y, b.z, b.w};
    __nv_bfloat16 hi[8], lo[8];
#pragma unroll
    for (int j = 0; j < 8; j++) {
        hi[j] = __float2bfloat16(v[j]);
        lo[j] = __float2bfloat16(v[j] - __bfloat162float(hi[j]));
    }
    *reinterpret_cast<uint4*>(&g_Bhi[dst + k]) = *reinterpret_cast<uint4*>(hi);
    *reinterpret_cast<uint4*>(&g_Blo[dst + k]) = *reinterpret_cast<uint4*>(lo);
}

// ---------------------------------------------------------------------------
// X0 split.
// ---------------------------------------------------------------------------
__global__ __launch_bounds__(256) void split_x0(const float* __restrict__ X0)
{
    const size_t base = ((size_t)blockIdx.x * 256 + threadIdx.x) * 16;
#pragma unroll
    for (int cidx = 0; cidx < 4; cidx++) {
        const size_t idx = base + cidx * 4;
        float4 v = *reinterpret_cast<const float4*>(X0 + idx);
        float vv[4] = {v.x, v.y, v.z, v.w};
        __nv_bfloat16 hi[4], lo[4];
#pragma unroll
        for (int j = 0; j < 4; j++) {
            hi[j] = __float2bfloat16(vv[j]);
            lo[j] = __float2bfloat16(vv[j] - __bfloat162float(hi[j]));
        }
        *reinterpret_cast<uint2*>(&g_Ahi[idx]) = *reinterpret_cast<uint2*>(hi);
        *reinterpret_cast<uint2*>(&g_Alo[idx]) = *reinterpret_cast<uint2*>(lo);
    }
}

// ---------------------------------------------------------------------------
// Gate logits: fp32 skinny GEMM, logit0[b, gl] = X0[b,:] . Wg[gl,:].
// ---------------------------------------------------------------------------
#define GL_BM 128
#define GL_BK 64
__global__ __launch_bounds__(256) void gate_logits(
    const float* __restrict__ X0, const float* __restrict__ Wg)
{
    __shared__ float As[GL_BK][GL_BM + 1];
    __shared__ float Ws[GL_BK][36];
    const int tid = threadIdx.x;
    const int m0 = blockIdx.x * GL_BM;
    const int row = tid >> 1;
    const int ch = (tid & 1) * 12;
    float acc[12];
#pragma unroll
    for (int j = 0; j < 12; j++) acc[j] = 0.f;

    for (int kc = 0; kc < D_DIM; kc += GL_BK) {
#pragma unroll
        for (int i = 0; i < 8; i++) {
            const int idx = i * 256 + tid;
            const int r = idx >> 4, c4 = (idx & 15) * 4;
            float4 v = *reinterpret_cast<const float4*>(
                X0 + (size_t)(m0 + r) * D_DIM + kc + c4);
            As[c4 + 0][r] = v.x; As[c4 + 1][r] = v.y;
            As[c4 + 2][r] = v.z; As[c4 + 3][r] = v.w;
        }
#pragma unroll
        for (int i = 0; i < 2; i++) {
            const int idx = i * 256 + tid;
            if (idx < 384) {
                const int r = idx >> 4, c4 = (idx & 15) * 4;
                float4 v = *reinterpret_cast<const float4*>(
                    Wg + (size_t)r * D_DIM + kc + c4);
                Ws[c4 + 0][r] = v.x; Ws[c4 + 1][r] = v.y;
                Ws[c4 + 2][r] = v.z; Ws[c4 + 3][r] = v.w;
            }
        }
        __syncthreads();
#pragma unroll 8
        for (int kk = 0; kk < GL_BK; kk++) {
            const float a = As[kk][row];
            float4 w0 = *reinterpret_cast<float4*>(&Ws[kk][ch]);
            float4 w1 = *reinterpret_cast<float4*>(&Ws[kk][ch + 4]);
            float4 w2 = *reinterpret_cast<float4*>(&Ws[kk][ch + 8]);
            acc[0] += a * w0.x; acc[1] += a * w0.y;
            acc[2] += a * w0.z; acc[3] += a * w0.w;
            acc[4] += a * w1.x; acc[5] += a * w1.y;
            acc[6] += a * w1.z; acc[7] += a * w1.w;
            acc[8] += a * w2.x; acc[9] += a * w2.y;
            acc[10] += a * w2.z; acc[11] += a * w2.w;
        }
        __syncthreads();
    }
    float* dst = g_logit + (size_t)(m0 + row) * NEXP + ch;
#pragma unroll
    for (int j = 0; j < 12; j++) dst[j] = acc[j];
}

// ---------------------------------------------------------------------------
// HMMA GEMM with fused expert-sum epilogue.
// Grid (24 experts, 128 m-tiles). 128 threads = 4 warps (2m x 2n),
// warp tile 64x64. 2 CTAs/SM (96 KB smem, <=256 regs). Tile nt = one expert.
// ---------------------------------------------------------------------------
__global__ __launch_bounds__(128, 2) void gemm_hmma()
{
    extern __shared__ char smem[];
    const uint32_t sb = smem_u32(smem);
    const int tid = threadIdx.x;
    const int lane = tid & 31, warp = tid >> 5;
    const int wm = warp & 1, wn = warp >> 1;     // 2m x 2n
    const int nt = blockIdx.x;                    // 0..23 (global expert)
    const int m0 = blockIdx.y * BM;
    const size_t brow0 = (size_t)nt * BN;

    float acc[4][8][4];
#pragma unroll
    for (int mi = 0; mi < 4; mi++)
#pragma unroll
        for (int ni = 0; ni < 8; ni++)
#pragma unroll
            for (int j = 0; j < 4; j++) acc[mi][ni][j] = 0.f;

    auto load_stage = [&](int step) {
        if (step < NSTEPS) {
            const int p = (step >= 2 * KSTEPS) ? 2 : (step >= KSTEPS ? 1 : 0);
            const int k0 = (step - p * KSTEPS) * KB;
            const __nv_bfloat16* Asrc = (p == 1) ? g_Alo : g_Ahi;
            const __nv_bfloat16* Bsrc = (p == 2) ? g_Blo : g_Bhi;
            const uint32_t a_base = sb + (step % STAGES) * STAGE_BYTES;
            const uint32_t b_base = a_base + A_BYTES;
#pragma unroll
            for (int i = 0; i < 8; i++) {
                const int idx = i * 128 + tid;
                const int r = idx >> 3, c = idx & 7;
                cpa16(a_base + swz(r * 128 + c * 16),
                      Asrc + (size_t)(m0 + r) * D_DIM + k0 + c * 8);
            }
#pragma unroll
            for (int i = 0; i < 8; i++) {
                const int idx = i * 128 + tid;
                const int r = idx >> 3, c = idx & 7;
                cpa16(b_base + swz(r * 128 + c * 16),
                      Bsrc + (brow0 + r) * D_DIM + k0 + c * 8);
            }
        }
        cpa_commit();
    };

    load_stage(0); load_stage(1);

    const int arow = wm * 64 + (lane & 15);
    const int brow = wn * 64 + (lane & 15);
    const int khalf = (lane >> 4) * 16;

    for (int step = 0; step < NSTEPS; ++step) {
        cpa_wait1();
        __syncthreads();
        load_stage(step + 2);

        const uint32_t a_base = sb + (step % STAGES) * STAGE_BYTES;
        const uint32_t b_base = a_base + A_BYTES;
#pragma unroll
        for (int k16 = 0; k16 < 4; k16++) {
            const int kb = k16 * 32 + khalf;
            uint32_t a[4][4], bb[4][4];
#pragma unroll
            for (int mi = 0; mi < 4; mi++)
                ldsm_x4(a[mi], a_base + swz((arow + mi * 16) * 128 + kb));
#pragma unroll
            for (int nj = 0; nj < 4; nj++)
                ldsm_x4(bb[nj], b_base + swz((brow + nj * 16) * 128 + kb));
#pragma unroll
            for (int mi = 0; mi < 4; mi++)
#pragma unroll
                for (int ni = 0; ni < 8; ni++)
                    mma16816(acc[mi][ni], a[mi],
                             bb[ni >> 1][ni & 1], bb[ni >> 1][(ni & 1) + 2]);
        }
    }

    // ---- Fused epilogue: pair products -> per-row expert sum ----
    __syncthreads();
    float* esum = reinterpret_cast<float*>(smem);   // [128]
    esum[tid] = 0.f;
    __syncthreads();

#pragma unroll
    for (int mi = 0; mi < 4; mi++) {
        float pl = 0.f, ph = 0.f;
#pragma unroll
        for (int ni = 0; ni < 8; ni++) {
            pl += acc[mi][ni][0] * acc[mi][ni][1];
            ph += acc[mi][ni][2] * acc[mi][ni][3];
        }
        pl += __shfl_xor_sync(0xffffffffu, pl, 1);
        pl += __shfl_xor_sync(0xffffffffu, pl, 2);
        ph += __shfl_xor_sync(0xffffffffu, ph, 1);
        ph += __shfl_xor_sync(0xffffffffu, ph, 2);
        if ((lane & 3) == 0) {
            const int r = wm * 64 + mi * 16 + (lane >> 2);
            atomicAdd(&esum[r], pl);
            atomicAdd(&esum[r + 8], ph);
        }
    }
    __syncthreads();
    g_e0[(size_t)(m0 + tid) * NEXP + nt] = esum[tid];
}

// ---------------------------------------------------------------------------
// Finalize: scalar recurrence from precomputed logits/e0, out = c * X0.
// ---------------------------------------------------------------------------
__global__ __launch_bounds__(256) void finalize(
    const float* __restrict__ X0, const float* __restrict__ bg,
    float* __restrict__ out)
{
    __shared__ float sc;
    const int b = blockIdx.x, t = threadIdx.x;

    if (t == 0) {
        const float* e0 = g_e0 + (size_t)b * NEXP;
        const float* lg = g_logit + (size_t)b * NEXP;
        float c = 1.f;
#pragma unroll
        for (int l = 0; l < L_LAYERS; l++) {
            const int base = l * E_EXP;
            float logit[E_EXP], mx = -1e30f;
#pragma unroll
            for (int e = 0; e < E_EXP; e++) {
                logit[e] = c * lg[base + e] + bg[base + e];
                mx = fmaxf(mx, logit[e]);
            }
            float se = 0.f, acc = 0.f;
#pragma unroll
            for (int e = 0; e < E_EXP; e++) {
                const float ge = expf(logit[e] - mx);
                se += ge;
                acc += ge * e0[base + e];
            }
            c += c * c * (acc / se);
        }
        sc = c;
    }
    __syncthreads();

    const float c = sc;
    const float4* x04 = reinterpret_cast<const float4*>(X0 + (size_t)b * D_DIM);
    float4* o4 = reinterpret_cast<float4*>(out + (size_t)b * D_DIM);
#pragma unroll
    for (int cidx = 0; cidx < 2; cidx++) {
        const int j = t + cidx * 256;
        float4 x = x04[j];
        x.x *= c; x.y *= c; x.z *= c; x.w *= c;
        o4[j] = x;
    }
}

// ---------------------------------------------------------------------------
// Launch
// ---------------------------------------------------------------------------
extern "C" void kernel_launch(void* const* d_in, const int* in_sizes, int n_in,
                              void* d_out, int out_size) {
    const float* X0 = (const float*)d_in[0];
    const float* U  = (const float*)d_in[1];
    const float* V  = (const float*)d_in[2];
    const float* Wg = (const float*)d_in[3];
    const float* bg = (const float*)d_in[4];
    float* out = (float*)d_out;

    cudaFuncSetAttribute(gemm_hmma, cudaFuncAttributeMaxDynamicSharedMemorySize,
                         SMEM_TOTAL);

    prep_weights<<<NCOL, 256>>>(U, V);
    split_x0<<<(B_ROWS * D_DIM) / (256 * 16), 256>>>(X0);
    gate_logits<<<B_ROWS / GL_BM, 256>>>(X0, Wg);
    gemm_hmma<<<dim3(NEXP, B_ROWS / BM), 128, SMEM_TOTAL>>>();
    finalize<<<B_ROWS, 256>>>(X0, bg, out);
}